// round 1
// baseline (speedup 1.0000x reference)
#include <cuda_runtime.h>
#include <cuda_bf16.h>
#include <mma.h>
#include <math.h>

using namespace nvcuda;

// Problem dims
#define BB 128
#define HH 600
#define RR 200
#define VV 50257
#define H2 1200
#define H4 2400

// padded leading dims (multiples of 64 so full WMMA tile stores are safe)
#define LDG_GATE 2432     // ceil(2400/64)*64
#define LDG_U    1216     // ceil(1200/64)*64
#define LDG_NH   1216
#define LDG_LOG  50304    // ceil(50257/64)*64

// Output offsets (fp32, tuple flattened in order)
#define OFF_OUTPROB 0
#define OFF_LOGATT  (BB*VV)                    // 6432896
#define OFF_PCOPY   (OFF_LOGATT + BB*RR)       // 6458496
#define OFF_NHOUT   (OFF_PCOPY + BB)           // 6458624
#define OFF_NEWCELL (OFF_NHOUT + 2*BB*HH)      // 6612224

// ---------------- scratch (device globals; no runtime alloc) ----------------
__device__ float d_x[BB*HH];            // embedded input
__device__ float d_Gf[BB*LDG_GATE];     // forward gates (pre-bias)
__device__ float d_Gb[BB*LDG_GATE];     // backward gates (pre-bias)
__device__ float d_cat[BB*H4];          // [h | selected] concat, row stride 2400
__device__ float d_u[BB*LDG_U];         // h @ W_lin
__device__ float d_hb[BB];              // h . b_lin
__device__ float d_scores[BB*RR];
__device__ float d_att[BB*RR];
__device__ float d_nh[BB*LDG_NH];       // pre-tanh then tanh'd in place
__device__ float d_logits[BB*LDG_LOG];  // ~25.8 MB

// ---------------- generic tf32 WMMA GEMM: C[M=128, N] -------------------
// transB=1: C = A @ W^T  (W row-major [N, K], ldw = row stride)
// transB=0: C = A @ W    (W row-major [K, N], ldw = N row stride)
// No bias/activation; consumers handle epilogues. ldc padded to mult of 64.
#define TM 128
#define TN 64
#define TK 40
#define SPAD 48

__global__ __launch_bounds__(256) void gemm_tf32(
    const float* __restrict__ A, int lda,
    const float* __restrict__ W, int ldw, int transB,
    float* __restrict__ C, int ldc, int N, int K)
{
    __shared__ float Asm[TM*SPAD];
    __shared__ float Wsm[TN*SPAD];
    const int tid  = threadIdx.x;
    const int warp = tid >> 5;
    const int wr   = warp >> 1;   // 0..3 -> 32-row group
    const int wc   = warp & 1;    // 0..1 -> 32-col group
    const int n0   = blockIdx.x * TN;

    wmma::fragment<wmma::accumulator,16,16,8,float> acc[2][2];
    #pragma unroll
    for (int i=0;i<2;i++)
        #pragma unroll
        for (int j=0;j<2;j++) wmma::fill_fragment(acc[i][j], 0.0f);

    for (int k0 = 0; k0 < K; k0 += TK) {
        #pragma unroll
        for (int idx = tid; idx < TM*TK; idx += 256) {
            int m = idx / TK, k = idx % TK;
            Asm[m*SPAD + k] = A[(long)m*lda + k0 + k];
        }
        if (transB) {
            #pragma unroll
            for (int idx = tid; idx < TN*TK; idx += 256) {
                int n = idx / TK, k = idx % TK;
                int gn = n0 + n;
                Wsm[n*SPAD + k] = (gn < N) ? W[(long)gn*ldw + k0 + k] : 0.0f;
            }
        } else {
            #pragma unroll
            for (int idx = tid; idx < TN*TK; idx += 256) {
                int n = idx % TN, k = idx / TN;
                int gn = n0 + n;
                Wsm[n*SPAD + k] = (gn < N) ? W[(long)(k0+k)*ldw + gn] : 0.0f;
            }
        }
        __syncthreads();

        #pragma unroll
        for (int ks = 0; ks < TK/8; ks++) {
            wmma::fragment<wmma::matrix_a,16,16,8,wmma::precision::tf32,wmma::row_major> af[2];
            wmma::fragment<wmma::matrix_b,16,16,8,wmma::precision::tf32,wmma::col_major> bf[2];
            #pragma unroll
            for (int i=0;i<2;i++) {
                wmma::load_matrix_sync(af[i], &Asm[(wr*32 + i*16)*SPAD + ks*8], SPAD);
                #pragma unroll
                for (int t=0;t<af[i].num_elements;t++) af[i].x[t] = wmma::__float_to_tf32(af[i].x[t]);
            }
            #pragma unroll
            for (int j=0;j<2;j++) {
                wmma::load_matrix_sync(bf[j], &Wsm[(wc*32 + j*16)*SPAD + ks*8], SPAD);
                #pragma unroll
                for (int t=0;t<bf[j].num_elements;t++) bf[j].x[t] = wmma::__float_to_tf32(bf[j].x[t]);
            }
            #pragma unroll
            for (int i=0;i<2;i++)
                #pragma unroll
                for (int j=0;j<2;j++)
                    wmma::mma_sync(acc[i][j], af[i], bf[j], acc[i][j]);
        }
        __syncthreads();
    }

    #pragma unroll
    for (int i=0;i<2;i++)
        #pragma unroll
        for (int j=0;j<2;j++) {
            int m0 = wr*32 + i*16;
            int c0 = n0 + wc*32 + j*16;
            wmma::store_matrix_sync(&C[(long)m0*ldc + c0], acc[i][j], ldc, wmma::mem_row_major);
        }
}

// ---------------- small kernels ----------------
__device__ __forceinline__ float sigmoidf_(float x) { return 1.0f / (1.0f + expf(-x)); }

__global__ void gather_emb(const int* __restrict__ word, const float* __restrict__ emb) {
    int idx = blockIdx.x*blockDim.x + threadIdx.x;
    if (idx >= BB*HH) return;
    int b = idx / HH, k = idx % HH;
    d_x[idx] = emb[(long)word[b]*HH + k];
}

__global__ void lstm_act(const float* __restrict__ bihf, const float* __restrict__ bhhf,
                         const float* __restrict__ bihb, const float* __restrict__ bhhb,
                         float* __restrict__ out_cell) {
    int idx = blockIdx.x*blockDim.x + threadIdx.x;
    if (idx >= BB*HH) return;
    int b = idx / HH, j = idx % HH;
    {
        const float* g = d_Gf + (long)b*LDG_GATE;
        float i_ = g[j]        + bihf[j]        + bhhf[j];
        float gg = g[H2 + j]   + bihf[H2 + j]   + bhhf[H2 + j];
        float o_ = g[1800 + j] + bihf[1800 + j] + bhhf[1800 + j];
        float c = sigmoidf_(i_) * tanhf(gg);
        float h = sigmoidf_(o_) * tanhf(c);
        d_cat[b*H4 + j] = h;
        out_cell[b*HH + j] = c;                 // new_cell[0]
    }
    {
        const float* g = d_Gb + (long)b*LDG_GATE;
        float i_ = g[j]        + bihb[j]        + bhhb[j];
        float gg = g[H2 + j]   + bihb[H2 + j]   + bhhb[H2 + j];
        float o_ = g[1800 + j] + bihb[1800 + j] + bhhb[1800 + j];
        float c = sigmoidf_(i_) * tanhf(gg);
        float h = sigmoidf_(o_) * tanhf(c);
        d_cat[b*H4 + HH + j] = h;
        out_cell[BB*HH + b*HH + j] = c;         // new_cell[1]
    }
}

__global__ void hb_kernel(const float* __restrict__ b_lin) {
    int w = (blockIdx.x*blockDim.x + threadIdx.x) >> 5;
    int lane = threadIdx.x & 31;
    if (w >= BB) return;
    const float* h = d_cat + (long)w*H4;     // first 1200 cols = h
    float s = 0.f;
    for (int k = lane; k < H2; k += 32) s += h[k]*b_lin[k];
    #pragma unroll
    for (int o = 16; o > 0; o >>= 1) s += __shfl_xor_sync(0xFFFFFFFFu, s, o);
    if (lane == 0) d_hb[w] = s;
}

// scores[b,r] = enc[b,r,:] . u[b,:] + hb[b]   (one warp per (b,r))
__global__ void scores_kernel(const float* __restrict__ enc) {
    int gw = (blockIdx.x*blockDim.x + threadIdx.x) >> 5;
    int lane = threadIdx.x & 31;
    if (gw >= BB*RR) return;
    int b = gw / RR, r = gw % RR;
    const float4* e4 = (const float4*)(enc + ((long)b*RR + r)*H2);
    const float4* u4 = (const float4*)(d_u + (long)b*LDG_U);
    float s = 0.f;
    #pragma unroll 4
    for (int k = lane; k < H2/4; k += 32) {
        float4 a = e4[k], c = u4[k];
        s += a.x*c.x + a.y*c.y + a.z*c.z + a.w*c.w;
    }
    #pragma unroll
    for (int o = 16; o > 0; o >>= 1) s += __shfl_xor_sync(0xFFFFFFFFu, s, o);
    if (lane == 0) d_scores[b*RR + r] = s + d_hb[b];
}

__global__ void att_softmax(float* __restrict__ log_att_out) {
    int b = blockIdx.x, t = threadIdx.x;
    __shared__ float red[256];
    float v = (t < RR) ? d_scores[b*RR + t] : -INFINITY;
    red[t] = v; __syncthreads();
    for (int s = 128; s > 0; s >>= 1) { if (t < s) red[t] = fmaxf(red[t], red[t+s]); __syncthreads(); }
    float mx = red[0]; __syncthreads();
    float ex = (t < RR) ? expf(v - mx) : 0.f;
    red[t] = ex; __syncthreads();
    for (int s = 128; s > 0; s >>= 1) { if (t < s) red[t] += red[t+s]; __syncthreads(); }
    float sum = red[0];
    if (t < RR) {
        log_att_out[b*RR + t] = v - mx - logf(sum);
        d_att[b*RR + t] = ex / sum;
    }
}

// selected[b,d] = sum_r att[b,r]*enc[b,r,d] -> cat[:,1200+d]
__global__ void selected_kernel(const float* __restrict__ enc) {
    int d = blockIdx.x*blockDim.x + threadIdx.x;
    int b = blockIdx.y;
    if (d >= H2) return;
    const float* e = enc + (long)b*RR*H2 + d;
    const float* a = d_att + b*RR;
    float s = 0.f;
    #pragma unroll 4
    for (int r = 0; r < RR; r++) s += a[r] * e[(long)r*H2];
    d_cat[b*H4 + H2 + d] = s;
}

__global__ void nh_act(const float* __restrict__ b_tanh, float* __restrict__ nh_out) {
    int idx = blockIdx.x*blockDim.x + threadIdx.x;
    if (idx >= BB*H2) return;
    int b = idx / H2, j = idx % H2;
    float v = tanhf(d_nh[(long)b*LDG_NH + j] + b_tanh[j]);
    d_nh[(long)b*LDG_NH + j] = v;
    int s = j / HH, hh = j % HH;
    nh_out[s*BB*HH + b*HH + hh] = v;
}

__global__ void pcopy_kernel(const float* __restrict__ W_sig, const float* __restrict__ b_sig,
                             float* __restrict__ out) {
    int w = (blockIdx.x*blockDim.x + threadIdx.x) >> 5;
    int lane = threadIdx.x & 31;
    if (w >= BB) return;
    const float* nh = d_nh + (long)w*LDG_NH;
    float s = 0.f;
    for (int k = lane; k < H2; k += 32) s += nh[k]*W_sig[k];
    #pragma unroll
    for (int o = 16; o > 0; o >>= 1) s += __shfl_xor_sync(0xFFFFFFFFu, s, o);
    if (lane == 0) out[w] = sigmoidf_(s + b_sig[0]);
}

__global__ __launch_bounds__(1024) void logsoftmax_v(const float* __restrict__ b_soft,
                                                     float* __restrict__ out) {
    int b = blockIdx.x, t = threadIdx.x;
    const float* x = d_logits + (long)b*LDG_LOG;
    __shared__ float red[1024];
    float mx = -INFINITY;
    for (int v = t; v < VV; v += 1024) mx = fmaxf(mx, x[v] + b_soft[v]);
    red[t] = mx; __syncthreads();
    for (int s = 512; s > 0; s >>= 1) { if (t < s) red[t] = fmaxf(red[t], red[t+s]); __syncthreads(); }
    mx = red[0]; __syncthreads();
    float sum = 0.f;
    for (int v = t; v < VV; v += 1024) sum += expf(x[v] + b_soft[v] - mx);
    red[t] = sum; __syncthreads();
    for (int s = 512; s > 0; s >>= 1) { if (t < s) red[t] += red[t+s]; __syncthreads(); }
    float lse = mx + logf(red[0]);
    for (int v = t; v < VV; v += 1024) out[(long)b*VV + v] = x[v] + b_soft[v] - lse;
}

// ---------------- launch ----------------
extern "C" void kernel_launch(void* const* d_in, const int* in_sizes, int n_in,
                              void* d_out, int out_size)
{
    const int*   word   = (const int*)  d_in[0];
    // d_in[1]=hidden, d_in[2]=cell : unused by the forward pass
    const float* enc    = (const float*)d_in[3];
    const float* emb    = (const float*)d_in[4];
    const float* W_ih_f = (const float*)d_in[5];
    const float* b_ih_f = (const float*)d_in[7];
    const float* b_hh_f = (const float*)d_in[8];
    const float* W_ih_b = (const float*)d_in[9];
    const float* b_ih_b = (const float*)d_in[11];
    const float* b_hh_b = (const float*)d_in[12];
    const float* W_lin  = (const float*)d_in[13];
    const float* b_lin  = (const float*)d_in[14];
    const float* W_tanh = (const float*)d_in[15];
    const float* b_tanh = (const float*)d_in[16];
    const float* W_soft = (const float*)d_in[17];
    const float* b_soft = (const float*)d_in[18];
    const float* W_sig  = (const float*)d_in[19];
    const float* b_sig  = (const float*)d_in[20];

    float* out = (float*)d_out;

    float *px, *pGf, *pGb, *pcat, *pu, *pnh, *plog;
    cudaGetSymbolAddress((void**)&px,   d_x);
    cudaGetSymbolAddress((void**)&pGf,  d_Gf);
    cudaGetSymbolAddress((void**)&pGb,  d_Gb);
    cudaGetSymbolAddress((void**)&pcat, d_cat);
    cudaGetSymbolAddress((void**)&pu,   d_u);
    cudaGetSymbolAddress((void**)&pnh,  d_nh);
    cudaGetSymbolAddress((void**)&plog, d_logits);

    // 1. embedding gather
    gather_emb<<<(BB*HH + 255)/256, 256>>>(word, emb);

    // 2. gate GEMMs: G = x @ W_ih^T   (M=128, N=2400, K=600)
    gemm_tf32<<<(H4 + TN - 1)/TN, 256>>>(px, HH, W_ih_f, HH, 1, pGf, LDG_GATE, H4, HH);
    gemm_tf32<<<(H4 + TN - 1)/TN, 256>>>(px, HH, W_ih_b, HH, 1, pGb, LDG_GATE, H4, HH);

    // 3. LSTM activations -> h into d_cat[:, :1200], new_cell -> out
    lstm_act<<<(BB*HH + 255)/256, 256>>>(b_ih_f, b_hh_f, b_ih_b, b_hh_b, out + OFF_NEWCELL);

    // 4. u = h @ W_lin  (M=128, N=1200, K=1200; W_lin used un-transposed)
    gemm_tf32<<<(H2 + TN - 1)/TN, 256>>>(pcat, H4, W_lin, H2, 0, pu, LDG_U, H2, H2);

    // 5. hb = h . b_lin
    hb_kernel<<<(BB*32 + 255)/256, 256>>>(b_lin);

    // 6. scores[b,r] = enc . u + hb   (warp per (b,r))
    scores_kernel<<<(BB*RR*32)/256, 256>>>(enc);

    // 7. softmax over R -> log_att (out) + att (scratch)
    att_softmax<<<BB, 256>>>(out + OFF_LOGATT);

    // 8. selected -> d_cat[:, 1200:]
    selected_kernel<<<dim3((H2 + 255)/256, BB), 256>>>(enc);

    // 9. nh_raw = cat @ W_tanh^T  (M=128, N=1200, K=2400)
    gemm_tf32<<<(H2 + TN - 1)/TN, 256>>>(pcat, H4, W_tanh, H4, 1, pnh, LDG_NH, H2, H4);

    // 10. nh = tanh(nh_raw + b_tanh); also write nh_out
    nh_act<<<(BB*H2 + 255)/256, 256>>>(b_tanh, out + OFF_NHOUT);

    // 11. p_copy
    pcopy_kernel<<<(BB*32 + 255)/256, 256>>>(W_sig, b_sig, out + OFF_PCOPY);

    // 12. logits = nh @ W_soft^T  (M=128, N=50257, K=1200)
    gemm_tf32<<<(VV + TN - 1)/TN, 256>>>(pnh, LDG_NH, W_soft, H2, 1, plog, LDG_LOG, VV, H2);

    // 13. out_prob = log_softmax(logits + b_soft)
    logsoftmax_v<<<BB, 1024>>>(b_soft, out + OFF_OUTPROB);
}

// round 2
// speedup vs baseline: 1.3606x; 1.3606x over previous
#include <cuda_runtime.h>
#include <cuda_bf16.h>
#include <mma.h>
#include <math.h>

using namespace nvcuda;

// Problem dims
#define BB 128
#define HH 600
#define RR 200
#define VV 50257
#define H2 1200
#define H4 2400

// padded leading dims (multiples of 128: full GEMM tile stores never cross rows)
#define LDG_GATE 2432     // 19*128
#define LDG_U    1280     // 10*128
#define LDG_NH   1280
#define LDG_LOG  50304    // 393*128

// Output offsets (fp32, tuple flattened in order)
#define OFF_OUTPROB 0
#define OFF_LOGATT  (BB*VV)
#define OFF_PCOPY   (OFF_LOGATT + BB*RR)
#define OFF_NHOUT   (OFF_PCOPY + BB)
#define OFF_NEWCELL (OFF_NHOUT + 2*BB*HH)

// ---------------- scratch (device globals; no runtime alloc) ----------------
__device__ float d_x[BB*HH];
__device__ float d_Gf[BB*LDG_GATE];
__device__ float d_Gb[BB*LDG_GATE];
__device__ float d_cat[BB*H4];          // [h | selected], row stride 2400
__device__ float d_u[BB*LDG_U];
__device__ float d_hb[BB];
__device__ float d_scores[BB*RR];
__device__ float d_att[BB*RR];
__device__ float d_nh[BB*LDG_NH];
__device__ float d_logits[BB*LDG_LOG];

// ---------------- pipelined tf32 GEMM: C[128, N] ----------------
// TRANSB=1: C = A @ W^T (W row-major [N,K]); TRANSB=0: C = A @ W (W [K,N])
#define TM 128
#define TN 128
#define TKP 40
#define SPA 44            // A row stride (floats); 44*4=176B, mult of 16
#define SPW1 44           // W smem row stride, transB=1
#define SPW0 132          // W smem row stride, transB=0; 132*4=528B mult 16
#define STAGE_T1 (TM*SPA + TN*SPW1)   // 11264 floats
#define STAGE_T0 (TM*SPA + TKP*SPW0)  // 10912 floats
#define NSTAGES 3

__device__ __forceinline__ void cp_async16(float* smem_ptr, const float* gptr, bool pred) {
    unsigned saddr = (unsigned)__cvta_generic_to_shared(smem_ptr);
    int sz = pred ? 16 : 0;
    asm volatile("cp.async.cg.shared.global [%0], [%1], 16, %2;\n"
                 :: "r"(saddr), "l"(gptr), "r"(sz));
}
__device__ __forceinline__ void cp_commit() {
    asm volatile("cp.async.commit_group;\n");
}
__device__ __forceinline__ void cp_wait2() {
    asm volatile("cp.async.wait_group 2;\n");
}

template<int TRANSB>
__global__ void __launch_bounds__(256) gemm_pipe(
    const float* __restrict__ A, int lda,
    const float* __restrict__ W, int ldw,
    float* __restrict__ C, int ldc, int N, int K)
{
    extern __shared__ float sm[];
    const int STAGE = TRANSB ? STAGE_T1 : STAGE_T0;
    const int tid  = threadIdx.x;
    const int warp = tid >> 5;
    const int wr   = warp >> 2;   // 0..1 -> 64-row group
    const int wc   = warp & 3;    // 0..3 -> 32-col group
    const int n0   = blockIdx.x * TN;
    const int KT   = K / TKP;

    wmma::fragment<wmma::accumulator,16,16,8,float> acc[4][2];
    #pragma unroll
    for (int i=0;i<4;i++)
        #pragma unroll
        for (int j=0;j<2;j++) wmma::fill_fragment(acc[i][j], 0.0f);

    auto load_tile = [&](int s, int k0) {
        float* As = sm + s*STAGE;
        float* Ws = As + TM*SPA;
        // A: 128 rows x 40 floats = 1280 16B chunks
        #pragma unroll
        for (int c = tid; c < TM*(TKP/4); c += 256) {
            int m = c / (TKP/4), kc = (c % (TKP/4))*4;
            cp_async16(As + m*SPA + kc, A + (long)m*lda + k0 + kc, true);
        }
        if (TRANSB) {
            #pragma unroll
            for (int c = tid; c < TN*(TKP/4); c += 256) {
                int n = c / (TKP/4), kc = (c % (TKP/4))*4;
                int gn = n0 + n;
                bool ok = gn < N;
                const float* src = W + (long)(ok ? gn : 0)*ldw + k0 + kc;
                cp_async16(Ws + n*SPW1 + kc, src, ok);
            }
        } else {
            #pragma unroll
            for (int c = tid; c < TKP*(TN/4); c += 256) {
                int kk = c / (TN/4), nc = (c % (TN/4))*4;
                int gn = n0 + nc;
                bool ok = gn < N;                 // N%4==0 so chunk fully in/out
                const float* src = W + (long)(k0+kk)*ldw + (ok ? gn : 0);
                cp_async16(Ws + kk*SPW0 + nc, src, ok);
            }
        }
        cp_commit();
    };

    auto compute = [&](int s) {
        float* As = sm + s*STAGE;
        float* Ws = As + TM*SPA;
        #pragma unroll
        for (int ks = 0; ks < TKP/8; ks++) {
            wmma::fragment<wmma::matrix_a,16,16,8,wmma::precision::tf32,wmma::row_major> af[4];
            #pragma unroll
            for (int i=0;i<4;i++) {
                wmma::load_matrix_sync(af[i], &As[(wr*64 + i*16)*SPA + ks*8], SPA);
                #pragma unroll
                for (int t=0;t<af[i].num_elements;t++) af[i].x[t] = wmma::__float_to_tf32(af[i].x[t]);
            }
            if constexpr (TRANSB) {
                wmma::fragment<wmma::matrix_b,16,16,8,wmma::precision::tf32,wmma::col_major> bf[2];
                #pragma unroll
                for (int j=0;j<2;j++) {
                    wmma::load_matrix_sync(bf[j], &Ws[(wc*32 + j*16)*SPW1 + ks*8], SPW1);
                    #pragma unroll
                    for (int t=0;t<bf[j].num_elements;t++) bf[j].x[t] = wmma::__float_to_tf32(bf[j].x[t]);
                }
                #pragma unroll
                for (int i=0;i<4;i++)
                    #pragma unroll
                    for (int j=0;j<2;j++) wmma::mma_sync(acc[i][j], af[i], bf[j], acc[i][j]);
            } else {
                wmma::fragment<wmma::matrix_b,16,16,8,wmma::precision::tf32,wmma::row_major> bf[2];
                #pragma unroll
                for (int j=0;j<2;j++) {
                    wmma::load_matrix_sync(bf[j], &Ws[(ks*8)*SPW0 + wc*32 + j*16], SPW0);
                    #pragma unroll
                    for (int t=0;t<bf[j].num_elements;t++) bf[j].x[t] = wmma::__float_to_tf32(bf[j].x[t]);
                }
                #pragma unroll
                for (int i=0;i<4;i++)
                    #pragma unroll
                    for (int j=0;j<2;j++) wmma::mma_sync(acc[i][j], af[i], bf[j], acc[i][j]);
            }
        }
    };

    load_tile(0, 0);
    if (KT > 1) load_tile(1, TKP); else cp_commit();

    for (int kt = 0; kt < KT; kt++) {
        if (kt + 2 < KT) load_tile((kt+2)%NSTAGES, (kt+2)*TKP);
        else cp_commit();
        cp_wait2();
        __syncthreads();
        compute(kt % NSTAGES);
        __syncthreads();
    }

    #pragma unroll
    for (int i=0;i<4;i++)
        #pragma unroll
        for (int j=0;j<2;j++) {
            int m0 = wr*64 + i*16;
            int c0 = n0 + wc*32 + j*16;
            wmma::store_matrix_sync(&C[(long)m0*ldc + c0], acc[i][j], ldc, wmma::mem_row_major);
        }
}

// ---------------- small kernels ----------------
__device__ __forceinline__ float sigmoidf_(float x) { return 1.0f / (1.0f + expf(-x)); }

__global__ void gather_emb(const int* __restrict__ word, const float* __restrict__ emb) {
    int idx = blockIdx.x*blockDim.x + threadIdx.x;
    if (idx >= BB*HH) return;
    int b = idx / HH, k = idx % HH;
    d_x[idx] = emb[(long)word[b]*HH + k];
}

__global__ void lstm_act(const float* __restrict__ bihf, const float* __restrict__ bhhf,
                         const float* __restrict__ bihb, const float* __restrict__ bhhb,
                         float* __restrict__ out_cell) {
    int idx = blockIdx.x*blockDim.x + threadIdx.x;
    if (idx >= BB*HH) return;
    int b = idx / HH, j = idx % HH;
    {
        const float* g = d_Gf + (long)b*LDG_GATE;
        float i_ = g[j]        + bihf[j]        + bhhf[j];
        float gg = g[H2 + j]   + bihf[H2 + j]   + bhhf[H2 + j];
        float o_ = g[1800 + j] + bihf[1800 + j] + bhhf[1800 + j];
        float c = sigmoidf_(i_) * tanhf(gg);
        float h = sigmoidf_(o_) * tanhf(c);
        d_cat[b*H4 + j] = h;
        out_cell[b*HH + j] = c;
    }
    {
        const float* g = d_Gb + (long)b*LDG_GATE;
        float i_ = g[j]        + bihb[j]        + bhhb[j];
        float gg = g[H2 + j]   + bihb[H2 + j]   + bhhb[H2 + j];
        float o_ = g[1800 + j] + bihb[1800 + j] + bhhb[1800 + j];
        float c = sigmoidf_(i_) * tanhf(gg);
        float h = sigmoidf_(o_) * tanhf(c);
        d_cat[b*H4 + HH + j] = h;
        out_cell[BB*HH + b*HH + j] = c;
    }
}

__global__ void hb_kernel(const float* __restrict__ b_lin) {
    int w = (blockIdx.x*blockDim.x + threadIdx.x) >> 5;
    int lane = threadIdx.x & 31;
    if (w >= BB) return;
    const float* h = d_cat + (long)w*H4;
    float s = 0.f;
    for (int k = lane; k < H2; k += 32) s += h[k]*b_lin[k];
    #pragma unroll
    for (int o = 16; o > 0; o >>= 1) s += __shfl_xor_sync(0xFFFFFFFFu, s, o);
    if (lane == 0) d_hb[w] = s;
}

__global__ void scores_kernel(const float* __restrict__ enc) {
    int gw = (blockIdx.x*blockDim.x + threadIdx.x) >> 5;
    int lane = threadIdx.x & 31;
    if (gw >= BB*RR) return;
    int b = gw / RR, r = gw % RR;
    const float4* e4 = (const float4*)(enc + ((long)b*RR + r)*H2);
    const float4* u4 = (const float4*)(d_u + (long)b*LDG_U);
    float s = 0.f;
    #pragma unroll 4
    for (int k = lane; k < H2/4; k += 32) {
        float4 a = e4[k], c = u4[k];
        s += a.x*c.x + a.y*c.y + a.z*c.z + a.w*c.w;
    }
    #pragma unroll
    for (int o = 16; o > 0; o >>= 1) s += __shfl_xor_sync(0xFFFFFFFFu, s, o);
    if (lane == 0) d_scores[b*RR + r] = s + d_hb[b];
}

__global__ void att_softmax(float* __restrict__ log_att_out) {
    int b = blockIdx.x, t = threadIdx.x;
    __shared__ float red[256];
    float v = (t < RR) ? d_scores[b*RR + t] : -INFINITY;
    red[t] = v; __syncthreads();
    for (int s = 128; s > 0; s >>= 1) { if (t < s) red[t] = fmaxf(red[t], red[t+s]); __syncthreads(); }
    float mx = red[0]; __syncthreads();
    float ex = (t < RR) ? expf(v - mx) : 0.f;
    red[t] = ex; __syncthreads();
    for (int s = 128; s > 0; s >>= 1) { if (t < s) red[t] += red[t+s]; __syncthreads(); }
    float sum = red[0];
    if (t < RR) {
        log_att_out[b*RR + t] = v - mx - logf(sum);
        d_att[b*RR + t] = ex / sum;
    }
}

__global__ void selected_kernel(const float* __restrict__ enc) {
    int d = blockIdx.x*blockDim.x + threadIdx.x;
    int b = blockIdx.y;
    if (d >= H2) return;
    const float* e = enc + (long)b*RR*H2 + d;
    const float* a = d_att + b*RR;
    float s = 0.f;
    #pragma unroll 4
    for (int r = 0; r < RR; r++) s += a[r] * e[(long)r*H2];
    d_cat[b*H4 + H2 + d] = s;
}

__global__ void nh_act(const float* __restrict__ b_tanh, float* __restrict__ nh_out) {
    int idx = blockIdx.x*blockDim.x + threadIdx.x;
    if (idx >= BB*H2) return;
    int b = idx / H2, j = idx % H2;
    float v = tanhf(d_nh[(long)b*LDG_NH + j] + b_tanh[j]);
    d_nh[(long)b*LDG_NH + j] = v;
    int s = j / HH, hh = j % HH;
    nh_out[s*BB*HH + b*HH + hh] = v;
}

__global__ void pcopy_kernel(const float* __restrict__ W_sig, const float* __restrict__ b_sig,
                             float* __restrict__ out) {
    int w = (blockIdx.x*blockDim.x + threadIdx.x) >> 5;
    int lane = threadIdx.x & 31;
    if (w >= BB) return;
    const float* nh = d_nh + (long)w*LDG_NH;
    float s = 0.f;
    for (int k = lane; k < H2; k += 32) s += nh[k]*W_sig[k];
    #pragma unroll
    for (int o = 16; o > 0; o >>= 1) s += __shfl_xor_sync(0xFFFFFFFFu, s, o);
    if (lane == 0) out[w] = sigmoidf_(s + b_sig[0]);
}

__global__ __launch_bounds__(1024) void logsoftmax_v(const float* __restrict__ b_soft,
                                                     float* __restrict__ out) {
    int b = blockIdx.x, t = threadIdx.x;
    const float* x = d_logits + (long)b*LDG_LOG;
    __shared__ float red[1024];
    float mx = -INFINITY;
    for (int v = t; v < VV; v += 1024) mx = fmaxf(mx, x[v] + b_soft[v]);
    red[t] = mx; __syncthreads();
    for (int s = 512; s > 0; s >>= 1) { if (t < s) red[t] = fmaxf(red[t], red[t+s]); __syncthreads(); }
    mx = red[0]; __syncthreads();
    float sum = 0.f;
    for (int v = t; v < VV; v += 1024) sum += expf(x[v] + b_soft[v] - mx);
    red[t] = sum; __syncthreads();
    for (int s = 512; s > 0; s >>= 1) { if (t < s) red[t] += red[t+s]; __syncthreads(); }
    float lse = mx + logf(red[0]);
    for (int v = t; v < VV; v += 1024) out[(long)b*VV + v] = x[v] + b_soft[v] - lse;
}

// ---------------- launch ----------------
extern "C" void kernel_launch(void* const* d_in, const int* in_sizes, int n_in,
                              void* d_out, int out_size)
{
    const int*   word   = (const int*)  d_in[0];
    const float* enc    = (const float*)d_in[3];
    const float* emb    = (const float*)d_in[4];
    const float* W_ih_f = (const float*)d_in[5];
    const float* b_ih_f = (const float*)d_in[7];
    const float* b_hh_f = (const float*)d_in[8];
    const float* W_ih_b = (const float*)d_in[9];
    const float* b_ih_b = (const float*)d_in[11];
    const float* b_hh_b = (const float*)d_in[12];
    const float* W_lin  = (const float*)d_in[13];
    const float* b_lin  = (const float*)d_in[14];
    const float* W_tanh = (const float*)d_in[15];
    const float* b_tanh = (const float*)d_in[16];
    const float* W_soft = (const float*)d_in[17];
    const float* b_soft = (const float*)d_in[18];
    const float* W_sig  = (const float*)d_in[19];
    const float* b_sig  = (const float*)d_in[20];

    float* out = (float*)d_out;

    float *px, *pGf, *pGb, *pcat, *pu, *pnh, *plog;
    cudaGetSymbolAddress((void**)&px,   d_x);
    cudaGetSymbolAddress((void**)&pGf,  d_Gf);
    cudaGetSymbolAddress((void**)&pGb,  d_Gb);
    cudaGetSymbolAddress((void**)&pcat, d_cat);
    cudaGetSymbolAddress((void**)&pu,   d_u);
    cudaGetSymbolAddress((void**)&pnh,  d_nh);
    cudaGetSymbolAddress((void**)&plog, d_logits);

    const int SM1 = NSTAGES*STAGE_T1*4;   // 135168 B
    const int SM0 = NSTAGES*STAGE_T0*4;   // 130944 B
    cudaFuncSetAttribute(gemm_pipe<1>, cudaFuncAttributeMaxDynamicSharedMemorySize, SM1);
    cudaFuncSetAttribute(gemm_pipe<0>, cudaFuncAttributeMaxDynamicSharedMemorySize, SM0);

    // 1. embedding gather
    gather_emb<<<(BB*HH + 255)/256, 256>>>(word, emb);

    // 2. gate GEMMs: G = x @ W_ih^T  (N=2400, K=600)
    gemm_pipe<1><<<LDG_GATE/TN, 256, SM1>>>(px, HH, W_ih_f, HH, pGf, LDG_GATE, H4, HH);
    gemm_pipe<1><<<LDG_GATE/TN, 256, SM1>>>(px, HH, W_ih_b, HH, pGb, LDG_GATE, H4, HH);

    // 3. LSTM activations
    lstm_act<<<(BB*HH + 255)/256, 256>>>(b_ih_f, b_hh_f, b_ih_b, b_hh_b, out + OFF_NEWCELL);

    // 4. u = h @ W_lin  (N=1200, K=1200, W not transposed)
    gemm_pipe<0><<<LDG_U/TN, 256, SM0>>>(pcat, H4, W_lin, H2, pu, LDG_U, H2, H2);

    // 5. hb = h . b_lin
    hb_kernel<<<(BB*32 + 255)/256, 256>>>(b_lin);

    // 6. scores
    scores_kernel<<<(BB*RR*32)/256, 256>>>(enc);

    // 7. softmax over R
    att_softmax<<<BB, 256>>>(out + OFF_LOGATT);

    // 8. selected
    selected_kernel<<<dim3((H2 + 255)/256, BB), 256>>>(enc);

    // 9. nh_raw = cat @ W_tanh^T  (N=1200, K=2400)
    gemm_pipe<1><<<LDG_NH/TN, 256, SM1>>>(pcat, H4, W_tanh, H4, pnh, LDG_NH, H2, H4);

    // 10. nh activation + nh_out
    nh_act<<<(BB*H2 + 255)/256, 256>>>(b_tanh, out + OFF_NHOUT);

    // 11. p_copy
    pcopy_kernel<<<(BB*32 + 255)/256, 256>>>(W_sig, b_sig, out + OFF_PCOPY);

    // 12. logits = nh @ W_soft^T  (N=50257, K=1200)
    gemm_pipe<1><<<LDG_LOG/TN, 256, SM1>>>(pnh, LDG_NH, W_soft, H2, plog, LDG_LOG, VV, H2);

    // 13. log_softmax over V
    logsoftmax_v<<<BB, 1024>>>(b_soft, out + OFF_OUTPROB);
}

// round 4
// speedup vs baseline: 3.0947x; 2.2746x over previous
#include <cuda_runtime.h>
#include <cuda_fp16.h>
#include <math.h>
#include <stdint.h>

// Problem dims
#define BB 128
#define HH 600
#define RR 200
#define VV 50257
#define H2 1200
#define H4 2400

// padded leading dims
#define LDG_GATE 2432
#define LDG_U    1280
#define LDG_NH   1280
#define LDG_LOG  50304

// Output offsets
#define OFF_OUTPROB 0
#define OFF_LOGATT  (BB*VV)
#define OFF_PCOPY   (OFF_LOGATT + BB*RR)
#define OFF_NHOUT   (OFF_PCOPY + BB)
#define OFF_NEWCELL (OFF_NHOUT + 2*BB*HH)

// ---------------- scratch ----------------
__device__ float d_x[BB*HH];
__device__ float d_Gf[BB*LDG_GATE];
__device__ float d_Gb[BB*LDG_GATE];
__device__ float d_cat[BB*H4];
__device__ float d_u[BB*LDG_U];
__device__ float d_hb[BB];
__device__ float d_scores[BB*RR];
__device__ float d_att[BB*RR];
__device__ float d_nh[BB*LDG_NH];
__device__ float d_logits[BB*LDG_LOG];
__device__ float d_WlinT[H2*H2];

// ---------------- fp16 mma.sync GEMM: C[128,N] = A[128,K](f32) @ W[N,K]^T(f32) ----------------
// Tile M=128 x N=128 x K=64(halfs). 256 threads = 8 warps (2 m-groups x 4 n-groups).
// smem per stage: A 128x72 halfs + W 128x72 halfs (stride 72 halfs = 144B: ldmatrix
// row-starts hit banks (36*r)%32 = 4r%32 -> conflict-free). Double buffered.
#define SROW   72
#define SROWB  144
#define STG_HALFS (128*SROW*2)       // A + W halfs per stage
#define STAGE_BYTES (STG_HALFS*2)    // 36864
#define GSMEM_BYTES (2*STAGE_BYTES)  // 73728

__device__ __forceinline__ uint32_t smem_u32_of(const void* p) {
    uint32_t a;
    asm("{ .reg .u64 t; cvta.to.shared.u64 t, %1; cvt.u32.u64 %0, t; }" : "=r"(a) : "l"(p));
    return a;
}
__device__ __forceinline__ void ldsm_x4(uint32_t& r0, uint32_t& r1, uint32_t& r2, uint32_t& r3,
                                        uint32_t addr) {
    asm volatile("ldmatrix.sync.aligned.m8n8.x4.shared.b16 {%0,%1,%2,%3}, [%4];"
                 : "=r"(r0), "=r"(r1), "=r"(r2), "=r"(r3) : "r"(addr));
}
__device__ __forceinline__ void mma16816(float* c, const uint32_t* a, const uint32_t* b) {
    asm volatile("mma.sync.aligned.m16n8k16.row.col.f32.f16.f16.f32 "
                 "{%0,%1,%2,%3}, {%4,%5,%6,%7}, {%8,%9}, {%0,%1,%2,%3};"
                 : "+f"(c[0]), "+f"(c[1]), "+f"(c[2]), "+f"(c[3])
                 : "r"(a[0]), "r"(a[1]), "r"(a[2]), "r"(a[3]), "r"(b[0]), "r"(b[1]));
}

__global__ void __launch_bounds__(256) gemm_mma(
    const float* __restrict__ A, int lda,
    const float* __restrict__ W, int ldw,
    float* __restrict__ C, int ldc, int N, int K)
{
    extern __shared__ __align__(16) __half sh[];
    const int tid  = threadIdx.x;
    const int warp = tid >> 5;
    const int lane = tid & 31;
    const int wm = warp >> 2;          // 0..1
    const int wn = warp & 3;           // 0..3
    const int n0 = blockIdx.x * 128;
    const int KT = (K + 63) >> 6;

    float acc[4][4][4];
    #pragma unroll
    for (int mi=0; mi<4; mi++)
        #pragma unroll
        for (int ni=0; ni<4; ni++)
            #pragma unroll
            for (int q=0; q<4; q++) acc[mi][ni][q] = 0.f;

    float4 ra[8], rw[8];
    const int rrow = tid >> 4;         // 0..15 base row group helper
    const int rkc  = tid & 15;

    // per-lane ldmatrix base byte-addresses (stage 0)
    const uint32_t sa = smem_u32_of(sh);
    const uint32_t aBase = sa
        + (uint32_t)((wm*64 + (lane & 7) + ((lane >> 3) & 1)*8) * SROWB)
        + (uint32_t)((lane >> 4) * 16);
    const uint32_t bBase = sa + (uint32_t)(128*SROWB)
        + (uint32_t)((wn*32 + (lane & 7) + (lane >> 4)*8) * SROWB)
        + (uint32_t)(((lane >> 3) & 1) * 16);

    auto ldg_tile = [&](int kt) {
        const int k0 = kt * 64;
        #pragma unroll
        for (int i = 0; i < 8; i++) {
            int row = rrow + i*16;
            int gk  = k0 + rkc*4;
            if (gk < K) ra[i] = *(const float4*)(A + (size_t)row*lda + gk);
            else        ra[i] = make_float4(0.f,0.f,0.f,0.f);
            int gn = n0 + row;
            if (gk < K && gn < N) rw[i] = *(const float4*)(W + (size_t)gn*ldw + gk);
            else                  rw[i] = make_float4(0.f,0.f,0.f,0.f);
        }
    };

    auto sts_tile = [&](int s) {
        __half* As = sh + (size_t)s * STG_HALFS;
        __half* Ws = As + 128*SROW;
        #pragma unroll
        for (int i = 0; i < 8; i++) {
            int row = rrow + i*16;
            uint32_t off = (uint32_t)row*SROW + (uint32_t)rkc*4;
            {
                __half2 p0 = __floats2half2_rn(ra[i].x, ra[i].y);
                __half2 p1 = __floats2half2_rn(ra[i].z, ra[i].w);
                uint2 v; v.x = *(uint32_t*)&p0; v.y = *(uint32_t*)&p1;
                *(uint2*)(As + off) = v;
            }
            {
                __half2 p0 = __floats2half2_rn(rw[i].x, rw[i].y);
                __half2 p1 = __floats2half2_rn(rw[i].z, rw[i].w);
                uint2 v; v.x = *(uint32_t*)&p0; v.y = *(uint32_t*)&p1;
                *(uint2*)(Ws + off) = v;
            }
        }
    };

    auto compute = [&](int s) {
        const uint32_t soff = (uint32_t)s * STAGE_BYTES;
        #pragma unroll
        for (int ks = 0; ks < 4; ks++) {
            uint32_t af[4][4];
            #pragma unroll
            for (int mb = 0; mb < 4; mb++)
                ldsm_x4(af[mb][0], af[mb][1], af[mb][2], af[mb][3],
                        aBase + soff + (uint32_t)(mb*16*SROWB) + (uint32_t)(ks*32));
            uint32_t bf[4][2];
            #pragma unroll
            for (int nb2 = 0; nb2 < 2; nb2++) {
                uint32_t r0, r1, r2, r3;
                ldsm_x4(r0, r1, r2, r3,
                        bBase + soff + (uint32_t)(nb2*16*SROWB) + (uint32_t)(ks*32));
                bf[nb2*2+0][0] = r0; bf[nb2*2+0][1] = r1;
                bf[nb2*2+1][0] = r2; bf[nb2*2+1][1] = r3;
            }
            #pragma unroll
            for (int mi = 0; mi < 4; mi++)
                #pragma unroll
                for (int ni = 0; ni < 4; ni++)
                    mma16816(acc[mi][ni], af[mi], bf[ni]);
        }
    };

    ldg_tile(0);
    for (int kt = 0; kt < KT; kt++) {
        const int s = kt & 1;
        sts_tile(s);
        __syncthreads();
        if (kt + 1 < KT) ldg_tile(kt + 1);
        compute(s);
        __syncthreads();
    }

    // epilogue: acc -> C (fp32). Thread lane mapping of m16n8 accum frag.
    const int er = lane >> 2;
    const int ec = (lane & 3) * 2;
    #pragma unroll
    for (int mi = 0; mi < 4; mi++) {
        #pragma unroll
        for (int ni = 0; ni < 4; ni++) {
            int row = wm*64 + mi*16 + er;
            int col = n0 + wn*32 + ni*8 + ec;
            float2 v0; v0.x = acc[mi][ni][0]; v0.y = acc[mi][ni][1];
            float2 v1; v1.x = acc[mi][ni][2]; v1.y = acc[mi][ni][3];
            *(float2*)(C + (size_t)row*ldc + col)     = v0;
            *(float2*)(C + (size_t)(row+8)*ldc + col) = v1;
        }
    }
}

// ---------------- transpose W_lin ----------------
__global__ void transpose_wlin(const float* __restrict__ Wl) {
    __shared__ float t[32][33];
    int x = blockIdx.x * 32 + threadIdx.x;
    int y = blockIdx.y * 32 + threadIdx.y;
    if (x < H2 && y < H2) t[threadIdx.y][threadIdx.x] = Wl[(size_t)y * H2 + x];
    __syncthreads();
    int ox = blockIdx.y * 32 + threadIdx.x;
    int oy = blockIdx.x * 32 + threadIdx.y;
    if (ox < H2 && oy < H2) d_WlinT[(size_t)oy * H2 + ox] = t[threadIdx.x][threadIdx.y];
}

// ---------------- small kernels ----------------
__device__ __forceinline__ float sigmoidf_(float x) { return 1.0f / (1.0f + expf(-x)); }

__global__ void gather_emb(const int* __restrict__ word, const float* __restrict__ emb) {
    int idx = blockIdx.x*blockDim.x + threadIdx.x;
    if (idx >= BB*HH) return;
    int b = idx / HH, k = idx % HH;
    d_x[idx] = emb[(long)word[b]*HH + k];
}

__global__ void lstm_act(const float* __restrict__ bihf, const float* __restrict__ bhhf,
                         const float* __restrict__ bihb, const float* __restrict__ bhhb,
                         float* __restrict__ out_cell) {
    int idx = blockIdx.x*blockDim.x + threadIdx.x;
    if (idx >= BB*HH) return;
    int b = idx / HH, j = idx % HH;
    {
        const float* g = d_Gf + (long)b*LDG_GATE;
        float i_ = g[j]        + bihf[j]        + bhhf[j];
        float gg = g[H2 + j]   + bihf[H2 + j]   + bhhf[H2 + j];
        float o_ = g[1800 + j] + bihf[1800 + j] + bhhf[1800 + j];
        float c = sigmoidf_(i_) * tanhf(gg);
        float h = sigmoidf_(o_) * tanhf(c);
        d_cat[b*H4 + j] = h;
        out_cell[b*HH + j] = c;
    }
    {
        const float* g = d_Gb + (long)b*LDG_GATE;
        float i_ = g[j]        + bihb[j]        + bhhb[j];
        float gg = g[H2 + j]   + bihb[H2 + j]   + bhhb[H2 + j];
        float o_ = g[1800 + j] + bihb[1800 + j] + bhhb[1800 + j];
        float c = sigmoidf_(i_) * tanhf(gg);
        float h = sigmoidf_(o_) * tanhf(c);
        d_cat[b*H4 + HH + j] = h;
        out_cell[BB*HH + b*HH + j] = c;
    }
}

__global__ void hb_kernel(const float* __restrict__ b_lin) {
    int w = (blockIdx.x*blockDim.x + threadIdx.x) >> 5;
    int lane = threadIdx.x & 31;
    if (w >= BB) return;
    const float* h = d_cat + (long)w*H4;
    float s = 0.f;
    for (int k = lane; k < H2; k += 32) s += h[k]*b_lin[k];
    #pragma unroll
    for (int o = 16; o > 0; o >>= 1) s += __shfl_xor_sync(0xFFFFFFFFu, s, o);
    if (lane == 0) d_hb[w] = s;
}

__global__ void scores_kernel(const float* __restrict__ enc) {
    int gw = (blockIdx.x*blockDim.x + threadIdx.x) >> 5;
    int lane = threadIdx.x & 31;
    if (gw >= BB*RR) return;
    int b = gw / RR, r = gw % RR;
    const float4* e4 = (const float4*)(enc + ((long)b*RR + r)*H2);
    const float4* u4 = (const float4*)(d_u + (long)b*LDG_U);
    float s = 0.f;
    #pragma unroll 4
    for (int k = lane; k < H2/4; k += 32) {
        float4 a = e4[k], c = u4[k];
        s += a.x*c.x + a.y*c.y + a.z*c.z + a.w*c.w;
    }
    #pragma unroll
    for (int o = 16; o > 0; o >>= 1) s += __shfl_xor_sync(0xFFFFFFFFu, s, o);
    if (lane == 0) d_scores[b*RR + r] = s + d_hb[b];
}

__global__ void att_softmax(float* __restrict__ log_att_out) {
    int b = blockIdx.x, t = threadIdx.x;
    __shared__ float red[256];
    float v = (t < RR) ? d_scores[b*RR + t] : -INFINITY;
    red[t] = v; __syncthreads();
    for (int s = 128; s > 0; s >>= 1) { if (t < s) red[t] = fmaxf(red[t], red[t+s]); __syncthreads(); }
    float mx = red[0]; __syncthreads();
    float ex = (t < RR) ? expf(v - mx) : 0.f;
    red[t] = ex; __syncthreads();
    for (int s = 128; s > 0; s >>= 1) { if (t < s) red[t] += red[t+s]; __syncthreads(); }
    float sum = red[0];
    if (t < RR) {
        log_att_out[b*RR + t] = v - mx - logf(sum);
        d_att[b*RR + t] = ex / sum;
    }
}

__global__ void selected_kernel(const float* __restrict__ enc) {
    int d = blockIdx.x*blockDim.x + threadIdx.x;
    int b = blockIdx.y;
    if (d >= H2) return;
    const float* e = enc + (long)b*RR*H2 + d;
    const float* a = d_att + b*RR;
    float s = 0.f;
    #pragma unroll 4
    for (int r = 0; r < RR; r++) s += a[r] * e[(long)r*H2];
    d_cat[b*H4 + H2 + d] = s;
}

__global__ void nh_act(const float* __restrict__ b_tanh, float* __restrict__ nh_out) {
    int idx = blockIdx.x*blockDim.x + threadIdx.x;
    if (idx >= BB*H2) return;
    int b = idx / H2, j = idx % H2;
    float v = tanhf(d_nh[(long)b*LDG_NH + j] + b_tanh[j]);
    d_nh[(long)b*LDG_NH + j] = v;
    int s = j / HH, hh = j % HH;
    nh_out[s*BB*HH + b*HH + hh] = v;
}

__global__ void pcopy_kernel(const float* __restrict__ W_sig, const float* __restrict__ b_sig,
                             float* __restrict__ out) {
    int w = (blockIdx.x*blockDim.x + threadIdx.x) >> 5;
    int lane = threadIdx.x & 31;
    if (w >= BB) return;
    const float* nh = d_nh + (long)w*LDG_NH;
    float s = 0.f;
    for (int k = lane; k < H2; k += 32) s += nh[k]*W_sig[k];
    #pragma unroll
    for (int o = 16; o > 0; o >>= 1) s += __shfl_xor_sync(0xFFFFFFFFu, s, o);
    if (lane == 0) out[w] = sigmoidf_(s + b_sig[0]);
}

__global__ __launch_bounds__(1024) void logsoftmax_v(const float* __restrict__ b_soft,
                                                     float* __restrict__ out) {
    int b = blockIdx.x, t = threadIdx.x;
    const float* x = d_logits + (long)b*LDG_LOG;
    __shared__ float red[1024];
    float mx = -INFINITY;
    for (int v = t; v < VV; v += 1024) mx = fmaxf(mx, x[v] + b_soft[v]);
    red[t] = mx; __syncthreads();
    for (int s = 512; s > 0; s >>= 1) { if (t < s) red[t] = fmaxf(red[t], red[t+s]); __syncthreads(); }
    mx = red[0]; __syncthreads();
    float sum = 0.f;
    for (int v = t; v < VV; v += 1024) sum += expf(x[v] + b_soft[v] - mx);
    red[t] = sum; __syncthreads();
    for (int s = 512; s > 0; s >>= 1) { if (t < s) red[t] += red[t+s]; __syncthreads(); }
    float lse = mx + logf(red[0]);
    for (int v = t; v < VV; v += 1024) out[(long)b*VV + v] = x[v] + b_soft[v] - lse;
}

// ---------------- launch ----------------
extern "C" void kernel_launch(void* const* d_in, const int* in_sizes, int n_in,
                              void* d_out, int out_size)
{
    const int*   word   = (const int*)  d_in[0];
    const float* enc    = (const float*)d_in[3];
    const float* emb    = (const float*)d_in[4];
    const float* W_ih_f = (const float*)d_in[5];
    const float* b_ih_f = (const float*)d_in[7];
    const float* b_hh_f = (const float*)d_in[8];
    const float* W_ih_b = (const float*)d_in[9];
    const float* b_ih_b = (const float*)d_in[11];
    const float* b_hh_b = (const float*)d_in[12];
    const float* W_lin  = (const float*)d_in[13];
    const float* b_lin  = (const float*)d_in[14];
    const float* W_tanh = (const float*)d_in[15];
    const float* b_tanh = (const float*)d_in[16];
    const float* W_soft = (const float*)d_in[17];
    const float* b_soft = (const float*)d_in[18];
    const float* W_sig  = (const float*)d_in[19];
    const float* b_sig  = (const float*)d_in[20];

    float* out = (float*)d_out;

    float *px, *pGf, *pGb, *pcat, *pu, *pnh, *plog, *pWlT;
    cudaGetSymbolAddress((void**)&px,   d_x);
    cudaGetSymbolAddress((void**)&pGf,  d_Gf);
    cudaGetSymbolAddress((void**)&pGb,  d_Gb);
    cudaGetSymbolAddress((void**)&pcat, d_cat);
    cudaGetSymbolAddress((void**)&pu,   d_u);
    cudaGetSymbolAddress((void**)&pnh,  d_nh);
    cudaGetSymbolAddress((void**)&plog, d_logits);
    cudaGetSymbolAddress((void**)&pWlT, d_WlinT);

    cudaFuncSetAttribute(gemm_mma, cudaFuncAttributeMaxDynamicSharedMemorySize, GSMEM_BYTES);

    // 1. embedding gather + W_lin transpose
    gather_emb<<<(BB*HH + 255)/256, 256>>>(word, emb);
    transpose_wlin<<<dim3(38,38), dim3(32,32)>>>(W_lin);

    // 2. gate GEMMs: G = x @ W_ih^T  (N=2400, K=600)
    gemm_mma<<<LDG_GATE/128, 256, GSMEM_BYTES>>>(px, HH, W_ih_f, HH, pGf, LDG_GATE, H4, HH);
    gemm_mma<<<LDG_GATE/128, 256, GSMEM_BYTES>>>(px, HH, W_ih_b, HH, pGb, LDG_GATE, H4, HH);

    // 3. LSTM activations
    lstm_act<<<(BB*HH + 255)/256, 256>>>(b_ih_f, b_hh_f, b_ih_b, b_hh_b, out + OFF_NEWCELL);

    // 4. u = h @ W_lin = h @ (WlinT)^T  (N=1200, K=1200)
    gemm_mma<<<LDG_U/128, 256, GSMEM_BYTES>>>(pcat, H4, pWlT, H2, pu, LDG_U, H2, H2);

    // 5. hb = h . b_lin
    hb_kernel<<<(BB*32 + 255)/256, 256>>>(b_lin);

    // 6. scores
    scores_kernel<<<(BB*RR*32)/256, 256>>>(enc);

    // 7. softmax over R
    att_softmax<<<BB, 256>>>(out + OFF_LOGATT);

    // 8. selected
    selected_kernel<<<dim3((H2 + 255)/256, BB), 256>>>(enc);

    // 9. nh_raw = cat @ W_tanh^T  (N=1200, K=2400)
    gemm_mma<<<LDG_NH/128, 256, GSMEM_BYTES>>>(pcat, H4, W_tanh, H4, pnh, LDG_NH, H2, H4);

    // 10. nh activation + nh_out
    nh_act<<<(BB*H2 + 255)/256, 256>>>(b_tanh, out + OFF_NHOUT);

    // 11. p_copy
    pcopy_kernel<<<(BB*32 + 255)/256, 256>>>(W_sig, b_sig, out + OFF_PCOPY);

    // 12. logits = nh @ W_soft^T  (N=50257, K=1200)
    gemm_mma<<<LDG_LOG/128, 256, GSMEM_BYTES>>>(pnh, LDG_NH, W_soft, H2, plog, LDG_LOG, VV, H2);

    // 13. log_softmax over V
    logsoftmax_v<<<BB, 1024>>>(b_soft, out + OFF_OUTPROB);
}

// round 5
// speedup vs baseline: 3.9368x; 1.2721x over previous
#include <cuda_runtime.h>
#include <cuda_fp16.h>
#include <math.h>
#include <stdint.h>

// Problem dims
#define BB 128
#define HH 600
#define RR 200
#define VV 50257
#define H2 1200
#define H4 2400

#define LDG_GATE 2432
#define LDG_U    1280
#define LDG_NH   1280
#define LDG_LOG  50304

// Output offsets
#define OFF_OUTPROB 0
#define OFF_LOGATT  (BB*VV)
#define OFF_PCOPY   (OFF_LOGATT + BB*RR)
#define OFF_NHOUT   (OFF_PCOPY + BB)
#define OFF_NEWCELL (OFF_NHOUT + 2*BB*HH)

// ---------------- scratch ----------------
#define SLICE (128*2560)
__device__ float d_part[8*SLICE];       // split-K partials (8 slices)
__device__ float d_x[BB*HH];
__device__ float d_cat[BB*H4];
__device__ float d_nh[BB*LDG_NH];
__device__ float d_logits[BB*LDG_LOG];
__device__ float d_WlinT[H2*H2];

// ---------------- mma.sync fp16 GEMM core ----------------
#define SROW   72
#define SROWB  144
#define STG_HALFS (128*SROW*2)
#define STAGE_BYTES (STG_HALFS*2)    // 36864
#define GSMEM_BYTES (2*STAGE_BYTES)  // 73728

__device__ __forceinline__ uint32_t smem_u32_of(const void* p) {
    uint32_t a;
    asm("{ .reg .u64 t; cvta.to.shared.u64 t, %1; cvt.u32.u64 %0, t; }" : "=r"(a) : "l"(p));
    return a;
}
__device__ __forceinline__ void ldsm_x4(uint32_t& r0, uint32_t& r1, uint32_t& r2, uint32_t& r3,
                                        uint32_t addr) {
    asm volatile("ldmatrix.sync.aligned.m8n8.x4.shared.b16 {%0,%1,%2,%3}, [%4];"
                 : "=r"(r0), "=r"(r1), "=r"(r2), "=r"(r3) : "r"(addr));
}
__device__ __forceinline__ void mma16816(float* c, const uint32_t* a, const uint32_t* b) {
    asm volatile("mma.sync.aligned.m16n8k16.row.col.f32.f16.f16.f32 "
                 "{%0,%1,%2,%3}, {%4,%5,%6,%7}, {%8,%9}, {%0,%1,%2,%3};"
                 : "+f"(c[0]), "+f"(c[1]), "+f"(c[2]), "+f"(c[3])
                 : "r"(a[0]), "r"(a[1]), "r"(a[2]), "r"(a[3]), "r"(b[0]), "r"(b[1]));
}

struct GemmCore {
    float acc[4][4][4];
    float4 ra[8], rw[8];
    int tid, warp, lane, wm, wn, rrow, rkc, n0;
    uint32_t aBase, bBase;
    const float* A; int lda;
    const float* W; int ldw;
    int N, K;

    __device__ __forceinline__ void init(const __half* sh, const float* A_, int lda_,
                                         const float* W_, int ldw_, int n0_, int N_, int K_) {
        A = A_; lda = lda_; W = W_; ldw = ldw_; n0 = n0_; N = N_; K = K_;
        tid = threadIdx.x; warp = tid >> 5; lane = tid & 31;
        wm = warp >> 2; wn = warp & 3;
        rrow = tid >> 4; rkc = tid & 15;
        uint32_t sa = smem_u32_of(sh);
        aBase = sa + (uint32_t)((wm*64 + (lane & 7) + ((lane >> 3) & 1)*8) * SROWB)
                   + (uint32_t)((lane >> 4) * 16);
        bBase = sa + (uint32_t)(128*SROWB)
                   + (uint32_t)((wn*32 + (lane & 7) + (lane >> 4)*8) * SROWB)
                   + (uint32_t)(((lane >> 3) & 1) * 16);
        #pragma unroll
        for (int mi=0; mi<4; mi++)
            #pragma unroll
            for (int ni=0; ni<4; ni++)
                #pragma unroll
                for (int q=0; q<4; q++) acc[mi][ni][q] = 0.f;
    }
    __device__ __forceinline__ void ldg_tile(int kt) {
        const int k0 = kt * 64;
        #pragma unroll
        for (int i = 0; i < 8; i++) {
            int row = rrow + i*16;
            int gk  = k0 + rkc*4;
            if (gk < K) ra[i] = *(const float4*)(A + (size_t)row*lda + gk);
            else        ra[i] = make_float4(0.f,0.f,0.f,0.f);
            int gn = n0 + row;
            if (gk < K && gn < N) rw[i] = *(const float4*)(W + (size_t)gn*ldw + gk);
            else                  rw[i] = make_float4(0.f,0.f,0.f,0.f);
        }
    }
    __device__ __forceinline__ void sts_tile(__half* sh, int s) {
        __half* As = sh + (size_t)s * STG_HALFS;
        __half* Ws = As + 128*SROW;
        #pragma unroll
        for (int i = 0; i < 8; i++) {
            int row = rrow + i*16;
            uint32_t off = (uint32_t)row*SROW + (uint32_t)rkc*4;
            {
                __half2 p0 = __floats2half2_rn(ra[i].x, ra[i].y);
                __half2 p1 = __floats2half2_rn(ra[i].z, ra[i].w);
                uint2 v; v.x = *(uint32_t*)&p0; v.y = *(uint32_t*)&p1;
                *(uint2*)(As + off) = v;
            }
            {
                __half2 p0 = __floats2half2_rn(rw[i].x, rw[i].y);
                __half2 p1 = __floats2half2_rn(rw[i].z, rw[i].w);
                uint2 v; v.x = *(uint32_t*)&p0; v.y = *(uint32_t*)&p1;
                *(uint2*)(Ws + off) = v;
            }
        }
    }
    __device__ __forceinline__ void compute(int s) {
        const uint32_t soff = (uint32_t)s * STAGE_BYTES;
        #pragma unroll
        for (int ks = 0; ks < 4; ks++) {
            uint32_t af[4][4];
            #pragma unroll
            for (int mb = 0; mb < 4; mb++)
                ldsm_x4(af[mb][0], af[mb][1], af[mb][2], af[mb][3],
                        aBase + soff + (uint32_t)(mb*16*SROWB) + (uint32_t)(ks*32));
            uint32_t bf[4][2];
            #pragma unroll
            for (int nb2 = 0; nb2 < 2; nb2++) {
                uint32_t r0, r1, r2, r3;
                ldsm_x4(r0, r1, r2, r3,
                        bBase + soff + (uint32_t)(nb2*16*SROWB) + (uint32_t)(ks*32));
                bf[nb2*2+0][0] = r0; bf[nb2*2+0][1] = r1;
                bf[nb2*2+1][0] = r2; bf[nb2*2+1][1] = r3;
            }
            #pragma unroll
            for (int mi = 0; mi < 4; mi++)
                #pragma unroll
                for (int ni = 0; ni < 4; ni++)
                    mma16816(acc[mi][ni], af[mi], bf[ni]);
        }
    }
    __device__ __forceinline__ void run(__half* sh, int kt0, int kt1) {
        ldg_tile(kt0);
        for (int kt = kt0; kt < kt1; kt++) {
            const int s = (kt - kt0) & 1;
            sts_tile(sh, s);
            __syncthreads();
            if (kt + 1 < kt1) ldg_tile(kt + 1);
            compute(s);
            __syncthreads();
        }
    }
    __device__ __forceinline__ void store(float* C, int ldc) {
        const int er = lane >> 2;
        const int ec = (lane & 3) * 2;
        #pragma unroll
        for (int mi = 0; mi < 4; mi++)
            #pragma unroll
            for (int ni = 0; ni < 4; ni++) {
                int row = wm*64 + mi*16 + er;
                int col = n0 + wn*32 + ni*8 + ec;
                float2 v0; v0.x = acc[mi][ni][0]; v0.y = acc[mi][ni][1];
                float2 v1; v1.x = acc[mi][ni][2]; v1.y = acc[mi][ni][3];
                *(float2*)(C + (size_t)row*ldc + col)     = v0;
                *(float2*)(C + (size_t)(row+8)*ldc + col) = v1;
            }
    }
};

// Direct GEMM (big W_soft): C = A @ W^T
__global__ void __launch_bounds__(256) gemm_mma(
    const float* __restrict__ A, int lda,
    const float* __restrict__ W, int ldw,
    float* __restrict__ C, int ldc, int N, int K)
{
    extern __shared__ __align__(16) __half sh[];
    GemmCore g;
    g.init(sh, A, lda, W, ldw, blockIdx.x*128, N, K);
    g.run(sh, 0, (K + 63) >> 6);
    g.store(C, ldc);
}

// Split-K GEMM: grid (nx, nsplit, nW). Writes partial to d_part slice (z*nsplit + y).
__global__ void __launch_bounds__(256) gemm_mma_split(
    const float* __restrict__ A, int lda,
    const float* __restrict__ W0, const float* __restrict__ W1, int ldw,
    int ldc, int N, int K)
{
    extern __shared__ __align__(16) __half sh[];
    const float* W = blockIdx.z ? W1 : W0;
    const int nsplit = gridDim.y;
    const int KT = (K + 63) >> 6;
    const int kt0 = (KT * blockIdx.y) / nsplit;
    const int kt1 = (KT * (blockIdx.y + 1)) / nsplit;
    GemmCore g;
    g.init(sh, A, lda, W, ldw, blockIdx.x*128, N, K);
    g.run(sh, kt0, kt1);
    const int slice = blockIdx.z * nsplit + blockIdx.y;
    g.store(d_part + (size_t)slice * SLICE, ldc);
}

// ---------------- transpose W_lin ----------------
__global__ void transpose_wlin(const float* __restrict__ Wl) {
    __shared__ float t[32][33];
    int x = blockIdx.x * 32 + threadIdx.x;
    int y = blockIdx.y * 32 + threadIdx.y;
    if (x < H2 && y < H2) t[threadIdx.y][threadIdx.x] = Wl[(size_t)y * H2 + x];
    __syncthreads();
    int ox = blockIdx.y * 32 + threadIdx.x;
    int oy = blockIdx.x * 32 + threadIdx.y;
    if (ox < H2 && oy < H2) d_WlinT[(size_t)oy * H2 + ox] = t[threadIdx.x][threadIdx.y];
}

// ---------------- small kernels ----------------
__device__ __forceinline__ float sigmoidf_(float x) { return 1.0f / (1.0f + expf(-x)); }

__global__ void gather_emb(const int* __restrict__ word, const float* __restrict__ emb) {
    int idx = blockIdx.x*blockDim.x + threadIdx.x;
    if (idx >= BB*HH) return;
    int b = idx / HH, k = idx % HH;
    d_x[idx] = emb[(long)word[b]*HH + k];
}

// sums 4 split-K partials per direction (slices 0-3 fwd, 4-7 bwd)
__global__ void lstm_act(const float* __restrict__ bihf, const float* __restrict__ bhhf,
                         const float* __restrict__ bihb, const float* __restrict__ bhhb,
                         float* __restrict__ out_cell) {
    int idx = blockIdx.x*blockDim.x + threadIdx.x;
    if (idx >= BB*HH) return;
    int b = idx / HH, j = idx % HH;
    #pragma unroll
    for (int z = 0; z < 2; z++) {
        const float* bih = z ? bihb : bihf;
        const float* bhh = z ? bhhb : bhhf;
        float i_ = 0.f, gg = 0.f, o_ = 0.f;
        #pragma unroll
        for (int s = 0; s < 4; s++) {
            const float* g = d_part + (size_t)(z*4+s)*SLICE + (size_t)b*LDG_GATE;
            i_ += g[j]; gg += g[H2 + j]; o_ += g[1800 + j];
        }
        i_ += bih[j]        + bhh[j];
        gg += bih[H2 + j]   + bhh[H2 + j];
        o_ += bih[1800 + j] + bhh[1800 + j];
        float c = sigmoidf_(i_) * tanhf(gg);
        float h = sigmoidf_(o_) * tanhf(c);
        d_cat[b*H4 + z*HH + j] = h;
        out_cell[z*BB*HH + b*HH + j] = c;
    }
}

// Fused attention: scores -> softmax -> log_att out + selected. One block per b.
// u[b] = sum of 8 split-K partials (ldc=1280). hb dropped: constant shift cancels in softmax.
__global__ void __launch_bounds__(1024) attn_fused(const float* __restrict__ enc,
                                                   float* __restrict__ log_att_out) {
    const int b = blockIdx.x;
    const int tid = threadIdx.x;
    const int warp = tid >> 5, lane = tid & 31;
    __shared__ float su[H2];
    __shared__ float satt[RR];
    __shared__ float s_mx, s_sum;

    for (int k = tid; k < H2; k += 1024) {
        float s = 0.f;
        #pragma unroll
        for (int p = 0; p < 8; p++) s += d_part[(size_t)p*SLICE + (size_t)b*LDG_U + k];
        su[k] = s;
    }
    __syncthreads();

    // scores: 32 warps, rows r = warp, warp+32, ...
    for (int r = warp; r < RR; r += 32) {
        const float4* e4 = (const float4*)(enc + ((size_t)b*RR + r)*H2);
        const float4* u4 = (const float4*)su;
        float s = 0.f;
        #pragma unroll 2
        for (int k = lane; k < H2/4; k += 32) {
            float4 a = e4[k], c = u4[k];
            s += a.x*c.x + a.y*c.y + a.z*c.z + a.w*c.w;
        }
        #pragma unroll
        for (int o = 16; o > 0; o >>= 1) s += __shfl_xor_sync(0xFFFFFFFFu, s, o);
        if (lane == 0) satt[r] = s;
    }
    __syncthreads();

    if (warp == 0) {
        float m = -INFINITY;
        for (int i = lane; i < RR; i += 32) m = fmaxf(m, satt[i]);
        #pragma unroll
        for (int o = 16; o > 0; o >>= 1) m = fmaxf(m, __shfl_xor_sync(0xFFFFFFFFu, m, o));
        float sm = 0.f;
        for (int i = lane; i < RR; i += 32) sm += expf(satt[i] - m);
        #pragma unroll
        for (int o = 16; o > 0; o >>= 1) sm += __shfl_xor_sync(0xFFFFFFFFu, sm, o);
        if (lane == 0) { s_mx = m; s_sum = sm; }
    }
    __syncthreads();
    const float lse = s_mx + logf(s_sum);
    for (int r = tid; r < RR; r += 1024) {
        float la = satt[r] - lse;
        log_att_out[(size_t)b*RR + r] = la;
        satt[r] = expf(la);
    }
    __syncthreads();

    // selected[d] = sum_r att[r] * enc[b][r][d]  (enc[b] hot in L2 from scores pass)
    for (int d = tid; d < H2; d += 1024) {
        const float* e = enc + (size_t)b*RR*H2 + d;
        float s = 0.f;
        #pragma unroll 4
        for (int r = 0; r < RR; r++) s += satt[r] * e[(size_t)r*H2];
        d_cat[b*H4 + H2 + d] = s;
    }
}

// nh = tanh(sum of 8 partials + b_tanh); writes d_nh and nh_out
__global__ void nh_act(const float* __restrict__ b_tanh, float* __restrict__ nh_out) {
    int idx = blockIdx.x*blockDim.x + threadIdx.x;
    if (idx >= BB*H2) return;
    int b = idx / H2, j = idx % H2;
    float v = b_tanh[j];
    #pragma unroll
    for (int p = 0; p < 8; p++) v += d_part[(size_t)p*SLICE + (size_t)b*LDG_NH + j];
    v = tanhf(v);
    d_nh[(size_t)b*LDG_NH + j] = v;
    int s = j / HH, hh = j % HH;
    nh_out[s*BB*HH + b*HH + hh] = v;
}

__global__ void pcopy_kernel(const float* __restrict__ W_sig, const float* __restrict__ b_sig,
                             float* __restrict__ out) {
    int w = (blockIdx.x*blockDim.x + threadIdx.x) >> 5;
    int lane = threadIdx.x & 31;
    if (w >= BB) return;
    const float* nh = d_nh + (size_t)w*LDG_NH;
    float s = 0.f;
    for (int k = lane; k < H2; k += 32) s += nh[k]*W_sig[k];
    #pragma unroll
    for (int o = 16; o > 0; o >>= 1) s += __shfl_xor_sync(0xFFFFFFFFu, s, o);
    if (lane == 0) out[w] = sigmoidf_(s + b_sig[0]);
}

// log-softmax over V with the whole row cached in smem (1 read + 1 write of logits)
#define LS_SMEM ((LDG_LOG + 1024) * 4)
__global__ void __launch_bounds__(1024) logsoftmax_v(const float* __restrict__ b_soft,
                                                     float* __restrict__ out) {
    extern __shared__ float sx[];
    float* red = sx + LDG_LOG;
    const int b = blockIdx.x, t = threadIdx.x;
    const float* x = d_logits + (size_t)b*LDG_LOG;
    float mx = -INFINITY;
    for (int v = t; v < VV; v += 1024) {
        float val = x[v] + b_soft[v];
        sx[v] = val;
        mx = fmaxf(mx, val);
    }
    red[t] = mx; __syncthreads();
    for (int s = 512; s > 0; s >>= 1) { if (t < s) red[t] = fmaxf(red[t], red[t+s]); __syncthreads(); }
    mx = red[0]; __syncthreads();
    float sum = 0.f;
    for (int v = t; v < VV; v += 1024) sum += expf(sx[v] - mx);
    red[t] = sum; __syncthreads();
    for (int s = 512; s > 0; s >>= 1) { if (t < s) red[t] += red[t+s]; __syncthreads(); }
    float lse = mx + logf(red[0]);
    for (int v = t; v < VV; v += 1024) out[(size_t)b*VV + v] = sx[v] - lse;
}

// ---------------- launch ----------------
extern "C" void kernel_launch(void* const* d_in, const int* in_sizes, int n_in,
                              void* d_out, int out_size)
{
    const int*   word   = (const int*)  d_in[0];
    const float* enc    = (const float*)d_in[3];
    const float* emb    = (const float*)d_in[4];
    const float* W_ih_f = (const float*)d_in[5];
    const float* b_ih_f = (const float*)d_in[7];
    const float* b_hh_f = (const float*)d_in[8];
    const float* W_ih_b = (const float*)d_in[9];
    const float* b_ih_b = (const float*)d_in[11];
    const float* b_hh_b = (const float*)d_in[12];
    const float* W_lin  = (const float*)d_in[13];
    const float* b_lin  = (const float*)d_in[14];  (void)b_lin; // cancels in log_softmax
    const float* W_tanh = (const float*)d_in[15];
    const float* b_tanh = (const float*)d_in[16];
    const float* W_soft = (const float*)d_in[17];
    const float* b_soft = (const float*)d_in[18];
    const float* W_sig  = (const float*)d_in[19];
    const float* b_sig  = (const float*)d_in[20];

    float* out = (float*)d_out;

    float *px, *pcat, *pnh, *plog, *pWlT;
    cudaGetSymbolAddress((void**)&px,   d_x);
    cudaGetSymbolAddress((void**)&pcat, d_cat);
    cudaGetSymbolAddress((void**)&pnh,  d_nh);
    cudaGetSymbolAddress((void**)&plog, d_logits);
    cudaGetSymbolAddress((void**)&pWlT, d_WlinT);

    cudaFuncSetAttribute(gemm_mma,       cudaFuncAttributeMaxDynamicSharedMemorySize, GSMEM_BYTES);
    cudaFuncSetAttribute(gemm_mma_split, cudaFuncAttributeMaxDynamicSharedMemorySize, GSMEM_BYTES);
    cudaFuncSetAttribute(logsoftmax_v,   cudaFuncAttributeMaxDynamicSharedMemorySize, LS_SMEM);

    // 1. embedding gather + W_lin transpose
    gather_emb<<<(BB*HH + 255)/256, 256>>>(word, emb);
    transpose_wlin<<<dim3(38,38), dim3(32,32)>>>(W_lin);

    // 2. both gate GEMMs, split-K x4: grid (19,4,2) = 152 blocks
    gemm_mma_split<<<dim3(19,4,2), 256, GSMEM_BYTES>>>(px, HH, W_ih_f, W_ih_b, HH,
                                                        LDG_GATE, H4, HH);

    // 3. LSTM activations (sums partials)
    lstm_act<<<(BB*HH + 255)/256, 256>>>(b_ih_f, b_hh_f, b_ih_b, b_hh_b, out + OFF_NEWCELL);

    // 4. u = h @ W_lin, split-K x8: grid (10,8) = 80 blocks
    gemm_mma_split<<<dim3(10,8,1), 256, GSMEM_BYTES>>>(pcat, H4, pWlT, pWlT, H2,
                                                        LDG_U, H2, H2);

    // 5. fused attention (scores + softmax + selected), sums u partials
    attn_fused<<<BB, 1024>>>(enc, out + OFF_LOGATT);

    // 6. nh_raw = cat @ W_tanh^T, split-K x8
    gemm_mma_split<<<dim3(10,8,1), 256, GSMEM_BYTES>>>(pcat, H4, W_tanh, W_tanh, H4,
                                                        LDG_NH, H2, H4);

    // 7. nh activation (sums partials) + nh_out
    nh_act<<<(BB*H2 + 255)/256, 256>>>(b_tanh, out + OFF_NHOUT);

    // 8. p_copy
    pcopy_kernel<<<(BB*32 + 255)/256, 256>>>(W_sig, b_sig, out + OFF_PCOPY);

    // 9. logits = nh @ W_soft^T (N=50257, K=1200), direct
    gemm_mma<<<LDG_LOG/128, 256, GSMEM_BYTES>>>(pnh, LDG_NH, W_soft, H2, plog, LDG_LOG, VV, H2);

    // 10. log_softmax over V (smem-cached)
    logsoftmax_v<<<BB, 1024, LS_SMEM>>>(b_soft, out + OFF_OUTPROB);
}

// round 8
// speedup vs baseline: 4.8102x; 1.2219x over previous
#include <cuda_runtime.h>
#include <cuda_fp16.h>
#include <math.h>
#include <stdint.h>

// Problem dims
#define BB 128
#define HH 600
#define RR 200
#define VV 50257
#define H2 1200
#define H4 2400

#define LDG_GATE 2432
#define LDG_U    1280
#define LDG_NH   1280
#define LDG_LOG  50304

// Output offsets
#define OFF_OUTPROB 0
#define OFF_LOGATT  (BB*VV)
#define OFF_PCOPY   (OFF_LOGATT + BB*RR)
#define OFF_NHOUT   (OFF_PCOPY + BB)
#define OFF_NEWCELL (OFF_NHOUT + 2*BB*HH)

// ---------------- scratch ----------------
#define SLICE (128*2560)
__device__ float  d_part[8*SLICE];
__device__ __align__(16) __half d_x_h[BB*HH];
__device__ __align__(16) __half d_cat_h[BB*H4];
__device__ __align__(16) __half d_nh_h[BB*LDG_NH];
__device__ float  d_logits[BB*LDG_LOG];
__device__ float  d_WlinT[H2*H2];

// ---------------- GEMM (tile 128x64, 2 CTAs/SM) ----------------
// smem: A stages 2 x 128x72 halfs (144B rows), W stages 2 x 64x72 halfs
#define SROWB 144
#define AST   18432
#define WST   9216
#define OFF_W (2*AST)            // 36864
#define GSMEM (OFF_W + 2*WST)    // 55296

__device__ __forceinline__ uint32_t smem_u32_of(const void* p) {
    uint32_t a;
    asm("{ .reg .u64 t; cvta.to.shared.u64 t, %1; cvt.u32.u64 %0, t; }" : "=r"(a) : "l"(p));
    return a;
}
__device__ __forceinline__ void ldsm_x4(uint32_t& r0, uint32_t& r1, uint32_t& r2, uint32_t& r3,
                                        uint32_t addr) {
    asm volatile("ldmatrix.sync.aligned.m8n8.x4.shared.b16 {%0,%1,%2,%3}, [%4];"
                 : "=r"(r0), "=r"(r1), "=r"(r2), "=r"(r3) : "r"(addr));
}
__device__ __forceinline__ void mma16816(float* c, const uint32_t* a, const uint32_t* b) {
    asm volatile("mma.sync.aligned.m16n8k16.row.col.f32.f16.f16.f32 "
                 "{%0,%1,%2,%3}, {%4,%5,%6,%7}, {%8,%9}, {%0,%1,%2,%3};"
                 : "+f"(c[0]), "+f"(c[1]), "+f"(c[2]), "+f"(c[3])
                 : "r"(a[0]), "r"(a[1]), "r"(a[2]), "r"(a[3]), "r"(b[0]), "r"(b[1]));
}

// C[128, 64-tile] = A[128,K](fp16) @ W[N,K]^T(fp32)
struct GemmCore {
    float acc[2][4][4];
    uint4  ra[4];
    float4 rw[4];
    int tid, lane, warp, wm, wn, n0;
    uint32_t sa, aPat, bPat;
    const __half* A; int lda;
    const float* W; int ldw;
    int N, K;
    char* smc;

    __device__ __forceinline__ void init(char* smc_, const __half* A_, int lda_,
                                         const float* W_, int ldw_, int n0_, int N_, int K_) {
        smc = smc_; A = A_; lda = lda_; W = W_; ldw = ldw_; n0 = n0_; N = N_; K = K_;
        tid = threadIdx.x; warp = tid >> 5; lane = tid & 31;
        wm = warp >> 1; wn = warp & 1;
        sa = smem_u32_of(smc);
        aPat = sa + (uint32_t)((wm*32 + (lane & 7) + ((lane >> 3) & 1)*8) * SROWB)
                  + (uint32_t)((lane >> 4) * 16);
        bPat = sa + (uint32_t)OFF_W
                  + (uint32_t)((wn*32 + (lane & 7) + (lane >> 4)*8) * SROWB)
                  + (uint32_t)(((lane >> 3) & 1) * 16);
        #pragma unroll
        for (int mi=0; mi<2; mi++)
            #pragma unroll
            for (int ni=0; ni<4; ni++)
                #pragma unroll
                for (int q=0; q<4; q++) acc[mi][ni][q] = 0.f;
    }

    __device__ __forceinline__ void ldg_tile(int kt) {
        const int k0 = kt * 64;
        // A: 128 rows x 8 chunks(16B) = 1024, 4/thread
        #pragma unroll
        for (int i = 0; i < 4; i++) {
            int idx = tid + i*256;
            int row = idx >> 3, c = idx & 7;
            int gk = k0 + c*8;
            if (gk < K) ra[i] = *(const uint4*)(A + (size_t)row*lda + gk);
            else        ra[i] = make_uint4(0,0,0,0);
        }
        // W: 64 rows x 16 chunks(4 floats) = 1024, 4/thread
        #pragma unroll
        for (int i = 0; i < 4; i++) {
            int idx = tid + i*256;
            int row = idx >> 4, c = idx & 15;
            int gk = k0 + c*4;
            int gn = n0 + row;
            if (gk < K && gn < N) rw[i] = *(const float4*)(W + (size_t)gn*ldw + gk);
            else                  rw[i] = make_float4(0.f,0.f,0.f,0.f);
        }
    }

    __device__ __forceinline__ void sts_tile(int s) {
        #pragma unroll
        for (int i = 0; i < 4; i++) {
            int idx = tid + i*256;
            int row = idx >> 3, c = idx & 7;
            *(uint4*)(smc + s*AST + row*SROWB + c*16) = ra[i];
        }
        #pragma unroll
        for (int i = 0; i < 4; i++) {
            int idx = tid + i*256;
            int row = idx >> 4, c = idx & 15;
            __half2 p0 = __floats2half2_rn(rw[i].x, rw[i].y);
            __half2 p1 = __floats2half2_rn(rw[i].z, rw[i].w);
            uint2 v; v.x = *(uint32_t*)&p0; v.y = *(uint32_t*)&p1;
            *(uint2*)(smc + OFF_W + s*WST + row*SROWB + c*8) = v;
        }
    }

    __device__ __forceinline__ void compute(int s) {
        const uint32_t aB = aPat + (uint32_t)(s*AST);
        const uint32_t bB = bPat + (uint32_t)(s*WST);
        #pragma unroll
        for (int ks = 0; ks < 4; ks++) {
            uint32_t af[2][4];
            #pragma unroll
            for (int mb = 0; mb < 2; mb++)
                ldsm_x4(af[mb][0], af[mb][1], af[mb][2], af[mb][3],
                        aB + (uint32_t)(mb*16*SROWB) + (uint32_t)(ks*32));
            uint32_t bf[4][2];
            #pragma unroll
            for (int nb2 = 0; nb2 < 2; nb2++) {
                uint32_t r0, r1, r2, r3;
                ldsm_x4(r0, r1, r2, r3,
                        bB + (uint32_t)(nb2*16*SROWB) + (uint32_t)(ks*32));
                bf[nb2*2+0][0] = r0; bf[nb2*2+0][1] = r1;
                bf[nb2*2+1][0] = r2; bf[nb2*2+1][1] = r3;
            }
            #pragma unroll
            for (int mi = 0; mi < 2; mi++)
                #pragma unroll
                for (int ni = 0; ni < 4; ni++)
                    mma16816(acc[mi][ni], af[mi], bf[ni]);
        }
    }

    __device__ __forceinline__ void run(int kt0, int kt1) {
        ldg_tile(kt0);
        for (int kt = kt0; kt < kt1; kt++) {
            const int s = (kt - kt0) & 1;
            sts_tile(s);
            __syncthreads();
            if (kt + 1 < kt1) ldg_tile(kt + 1);
            compute(s);
            __syncthreads();
        }
    }

    __device__ __forceinline__ void store(float* C, int ldc) {
        const int er = lane >> 2;
        const int ec = (lane & 3) * 2;
        #pragma unroll
        for (int mi = 0; mi < 2; mi++)
            #pragma unroll
            for (int ni = 0; ni < 4; ni++) {
                int row = wm*32 + mi*16 + er;
                int col = n0 + wn*32 + ni*8 + ec;
                float2 v0; v0.x = acc[mi][ni][0]; v0.y = acc[mi][ni][1];
                float2 v1; v1.x = acc[mi][ni][2]; v1.y = acc[mi][ni][3];
                *(float2*)(C + (size_t)row*ldc + col)     = v0;
                *(float2*)(C + (size_t)(row+8)*ldc + col) = v1;
            }
    }
};

// Direct GEMM (big W_soft)
__global__ void __launch_bounds__(256, 2) gemm_mma(
    const __half* __restrict__ A, int lda,
    const float* __restrict__ W, int ldw,
    float* __restrict__ C, int ldc, int N, int K)
{
    extern __shared__ __align__(16) char smc[];
    GemmCore g;
    g.init(smc, A, lda, W, ldw, blockIdx.x*64, N, K);
    g.run(0, (K + 63) >> 6);
    g.store(C, ldc);
}

// Split-K GEMM: grid (nx, nsplit, nW). Partial -> d_part slice (z*nsplit + y).
__global__ void __launch_bounds__(256, 2) gemm_mma_split(
    const __half* __restrict__ A, int lda,
    const float* __restrict__ W0, const float* __restrict__ W1, int ldw,
    int ldc, int N, int K)
{
    extern __shared__ __align__(16) char smc[];
    const float* W = blockIdx.z ? W1 : W0;
    const int nsplit = gridDim.y;
    const int KT = (K + 63) >> 6;
    const int kt0 = (KT * blockIdx.y) / nsplit;
    const int kt1 = (KT * (blockIdx.y + 1)) / nsplit;
    GemmCore g;
    g.init(smc, A, lda, W, ldw, blockIdx.x*64, N, K);
    g.run(kt0, kt1);
    const int slice = blockIdx.z * nsplit + blockIdx.y;
    g.store(d_part + (size_t)slice * SLICE, ldc);
}

// ---------------- transpose W_lin ----------------
__global__ void transpose_wlin(const float* __restrict__ Wl) {
    __shared__ float t[32][33];
    int x = blockIdx.x * 32 + threadIdx.x;
    int y = blockIdx.y * 32 + threadIdx.y;
    if (x < H2 && y < H2) t[threadIdx.y][threadIdx.x] = Wl[(size_t)y * H2 + x];
    __syncthreads();
    int ox = blockIdx.y * 32 + threadIdx.x;
    int oy = blockIdx.x * 32 + threadIdx.y;
    if (ox < H2 && oy < H2) d_WlinT[(size_t)oy * H2 + ox] = t[threadIdx.x][threadIdx.y];
}

// ---------------- small kernels ----------------
__device__ __forceinline__ float sigmoidf_(float x) { return 1.0f / (1.0f + expf(-x)); }

__global__ void gather_emb(const int* __restrict__ word, const float* __restrict__ emb) {
    int idx = blockIdx.x*blockDim.x + threadIdx.x;
    if (idx >= BB*HH) return;
    int b = idx / HH, k = idx % HH;
    d_x_h[idx] = __float2half(emb[(size_t)word[b]*HH + k]);
}

__global__ void lstm_act(const float* __restrict__ bihf, const float* __restrict__ bhhf,
                         const float* __restrict__ bihb, const float* __restrict__ bhhb,
                         float* __restrict__ out_cell) {
    int idx = blockIdx.x*blockDim.x + threadIdx.x;
    if (idx >= BB*HH) return;
    int b = idx / HH, j = idx % HH;
    #pragma unroll
    for (int z = 0; z < 2; z++) {
        const float* bih = z ? bihb : bihf;
        const float* bhh = z ? bhhb : bhhf;
        float i_ = 0.f, gg = 0.f, o_ = 0.f;
        #pragma unroll
        for (int s = 0; s < 4; s++) {
            const float* g = d_part + (size_t)(z*4+s)*SLICE + (size_t)b*LDG_GATE;
            i_ += g[j]; gg += g[H2 + j]; o_ += g[1800 + j];
        }
        i_ += bih[j]        + bhh[j];
        gg += bih[H2 + j]   + bhh[H2 + j];
        o_ += bih[1800 + j] + bhh[1800 + j];
        float c = sigmoidf_(i_) * tanhf(gg);
        float h = sigmoidf_(o_) * tanhf(c);
        d_cat_h[b*H4 + z*HH + j] = __float2half(h);
        out_cell[z*BB*HH + b*HH + j] = c;
    }
}

// Fused attention (one block per b); hb term dropped (cancels in log_softmax)
__global__ void __launch_bounds__(1024) attn_fused(const float* __restrict__ enc,
                                                   float* __restrict__ log_att_out) {
    const int b = blockIdx.x;
    const int tid = threadIdx.x;
    const int warp = tid >> 5, lane = tid & 31;
    __shared__ float su[H2];
    __shared__ float satt[RR];
    __shared__ float s_mx, s_sum;

    for (int k = tid; k < H2; k += 1024) {
        float s = 0.f;
        #pragma unroll
        for (int p = 0; p < 8; p++) s += d_part[(size_t)p*SLICE + (size_t)b*LDG_U + k];
        su[k] = s;
    }
    __syncthreads();

    for (int r = warp; r < RR; r += 32) {
        const float4* e4 = (const float4*)(enc + ((size_t)b*RR + r)*H2);
        const float4* u4 = (const float4*)su;
        float s = 0.f;
        #pragma unroll 2
        for (int k = lane; k < H2/4; k += 32) {
            float4 a = e4[k], c = u4[k];
            s += a.x*c.x + a.y*c.y + a.z*c.z + a.w*c.w;
        }
        #pragma unroll
        for (int o = 16; o > 0; o >>= 1) s += __shfl_xor_sync(0xFFFFFFFFu, s, o);
        if (lane == 0) satt[r] = s;
    }
    __syncthreads();

    if (warp == 0) {
        float m = -INFINITY;
        for (int i = lane; i < RR; i += 32) m = fmaxf(m, satt[i]);
        #pragma unroll
        for (int o = 16; o > 0; o >>= 1) m = fmaxf(m, __shfl_xor_sync(0xFFFFFFFFu, m, o));
        float sm = 0.f;
        for (int i = lane; i < RR; i += 32) sm += expf(satt[i] - m);
        #pragma unroll
        for (int o = 16; o > 0; o >>= 1) sm += __shfl_xor_sync(0xFFFFFFFFu, sm, o);
        if (lane == 0) { s_mx = m; s_sum = sm; }
    }
    __syncthreads();
    const float lse = s_mx + logf(s_sum);
    for (int r = tid; r < RR; r += 1024) {
        float la = satt[r] - lse;
        log_att_out[(size_t)b*RR + r] = la;
        satt[r] = expf(la);
    }
    __syncthreads();

    for (int d = tid; d < H2; d += 1024) {
        const float* e = enc + (size_t)b*RR*H2 + d;
        float s = 0.f;
        #pragma unroll 8
        for (int r = 0; r < RR; r++) s += satt[r] * e[(size_t)r*H2];
        d_cat_h[b*H4 + H2 + d] = __float2half(s);
    }
}

__global__ void nh_act(const float* __restrict__ b_tanh, float* __restrict__ nh_out) {
    int idx = blockIdx.x*blockDim.x + threadIdx.x;
    if (idx >= BB*H2) return;
    int b = idx / H2, j = idx % H2;
    float v = b_tanh[j];
    #pragma unroll
    for (int p = 0; p < 8; p++) v += d_part[(size_t)p*SLICE + (size_t)b*LDG_NH + j];
    v = tanhf(v);
    d_nh_h[(size_t)b*LDG_NH + j] = __float2half(v);
    int s = j / HH, hh = j % HH;
    nh_out[s*BB*HH + b*HH + hh] = v;
}

__global__ void pcopy_kernel(const float* __restrict__ W_sig, const float* __restrict__ b_sig,
                             float* __restrict__ out) {
    int w = (blockIdx.x*blockDim.x + threadIdx.x) >> 5;
    int lane = threadIdx.x & 31;
    if (w >= BB) return;
    const __half* nh = d_nh_h + (size_t)w*LDG_NH;
    float s = 0.f;
    for (int k = lane; k < H2; k += 32) s += __half2float(nh[k])*W_sig[k];
    #pragma unroll
    for (int o = 16; o > 0; o >>= 1) s += __shfl_xor_sync(0xFFFFFFFFu, s, o);
    if (lane == 0) out[w] = sigmoidf_(s + b_sig[0]);
}

#define LS_SMEM ((LDG_LOG + 1024) * 4)
__global__ void __launch_bounds__(1024) logsoftmax_v(const float* __restrict__ b_soft,
                                                     float* __restrict__ out) {
    extern __shared__ float sx[];
    float* red = sx + LDG_LOG;
    const int b = blockIdx.x, t = threadIdx.x;
    const float* x = d_logits + (size_t)b*LDG_LOG;
    float mx = -INFINITY;
    for (int v = t; v < VV; v += 1024) {
        float val = x[v] + b_soft[v];
        sx[v] = val;
        mx = fmaxf(mx, val);
    }
    red[t] = mx; __syncthreads();
    for (int s = 512; s > 0; s >>= 1) { if (t < s) red[t] = fmaxf(red[t], red[t+s]); __syncthreads(); }
    mx = red[0]; __syncthreads();
    float sum = 0.f;
    for (int v = t; v < VV; v += 1024) sum += expf(sx[v] - mx);
    red[t] = sum; __syncthreads();
    for (int s = 512; s > 0; s >>= 1) { if (t < s) red[t] += red[t+s]; __syncthreads(); }
    float lse = mx + logf(red[0]);
    for (int v = t; v < VV; v += 1024) out[(size_t)b*VV + v] = sx[v] - lse;
}

// ---------------- launch ----------------
extern "C" void kernel_launch(void* const* d_in, const int* in_sizes, int n_in,
                              void* d_out, int out_size)
{
    const int*   word   = (const int*)  d_in[0];
    const float* enc    = (const float*)d_in[3];
    const float* emb    = (const float*)d_in[4];
    const float* W_ih_f = (const float*)d_in[5];
    const float* b_ih_f = (const float*)d_in[7];
    const float* b_hh_f = (const float*)d_in[8];
    const float* W_ih_b = (const float*)d_in[9];
    const float* b_ih_b = (const float*)d_in[11];
    const float* b_hh_b = (const float*)d_in[12];
    const float* W_lin  = (const float*)d_in[13];
    const float* W_tanh = (const float*)d_in[15];
    const float* b_tanh = (const float*)d_in[16];
    const float* W_soft = (const float*)d_in[17];
    const float* b_soft = (const float*)d_in[18];
    const float* W_sig  = (const float*)d_in[19];
    const float* b_sig  = (const float*)d_in[20];

    float* out = (float*)d_out;

    __half *px, *pcat, *pnh;
    float *plog, *pWlT;
    cudaGetSymbolAddress((void**)&px,   d_x_h);
    cudaGetSymbolAddress((void**)&pcat, d_cat_h);
    cudaGetSymbolAddress((void**)&pnh,  d_nh_h);
    cudaGetSymbolAddress((void**)&plog, d_logits);
    cudaGetSymbolAddress((void**)&pWlT, d_WlinT);

    cudaFuncSetAttribute(gemm_mma,       cudaFuncAttributeMaxDynamicSharedMemorySize, GSMEM);
    cudaFuncSetAttribute(gemm_mma_split, cudaFuncAttributeMaxDynamicSharedMemorySize, GSMEM);
    cudaFuncSetAttribute(logsoftmax_v,   cudaFuncAttributeMaxDynamicSharedMemorySize, LS_SMEM);

    // 1. embedding gather + W_lin transpose
    gather_emb<<<(BB*HH + 255)/256, 256>>>(word, emb);
    transpose_wlin<<<dim3(38,38), dim3(32,32)>>>(W_lin);

    // 2. both gate GEMMs, split-K x4 x 2 dirs (304 blocks, 2 CTA/SM)
    gemm_mma_split<<<dim3(LDG_GATE/64,4,2), 256, GSMEM>>>(px, HH, W_ih_f, W_ih_b, HH,
                                                          LDG_GATE, H4, HH);

    // 3. LSTM activations (sums partials)
    lstm_act<<<(BB*HH + 255)/256, 256>>>(b_ih_f, b_hh_f, b_ih_b, b_hh_b, out + OFF_NEWCELL);

    // 4. u = h @ W_lin, split-K x8 (160 blocks)
    gemm_mma_split<<<dim3(LDG_U/64,8,1), 256, GSMEM>>>(pcat, H4, pWlT, pWlT, H2,
                                                       LDG_U, H2, H2);

    // 5. fused attention
    attn_fused<<<BB, 1024>>>(enc, out + OFF_LOGATT);

    // 6. nh_raw = cat @ W_tanh^T, split-K x8 (160 blocks)
    gemm_mma_split<<<dim3(LDG_NH/64,8,1), 256, GSMEM>>>(pcat, H4, W_tanh, W_tanh, H4,
                                                        LDG_NH, H2, H4);

    // 7. nh activation + nh_out
    nh_act<<<(BB*H2 + 255)/256, 256>>>(b_tanh, out + OFF_NHOUT);

    // 8. p_copy
    pcopy_kernel<<<(BB*32 + 255)/256, 256>>>(W_sig, b_sig, out + OFF_PCOPY);

    // 9. logits = nh @ W_soft^T (N=50257, K=1200), 786 blocks
    gemm_mma<<<LDG_LOG/64, 256, GSMEM>>>(pnh, LDG_NH, W_soft, H2, plog, LDG_LOG, VV, H2);

    // 10. log_softmax over V
    logsoftmax_v<<<BB, 1024, LS_SMEM>>>(b_soft, out + OFF_OUTPROB);
}